// round 3
// baseline (speedup 1.0000x reference)
#include <cuda_runtime.h>
#include <cstdint>
#include <cstddef>
#include <math.h>

// ---------------- problem constants ----------------
#define M_ROWS 4096      // B*N = 8*512
#define D_IN   4608
#define D_HID  4608
#define D_OUT  1152

// ---------------- GEMM tiling ----------------
#define BM 128
#define BN 128
#define BK 32
#define NTHREADS 512
#define ASTRIDE 36                      // 32 + 4 pad (floats) -> conflict-free a-frag LDS
#define BSTRIDE 136                     // 128 + 8 pad (floats) -> conflict-free b-frag LDS
#define STAGE_F (2*BM*ASTRIDE + BK*BSTRIDE)   // 9216 + 4352 = 13568 floats/stage
#define SMEM_BYTES (2*STAGE_F*4)              // 108544 bytes (double buffered)

// ---------------- device scratch (allocation-free rule: __device__ globals) ----
__device__ float g_hmu [(size_t)M_ROWS * D_HID];   // 75.5 MB
__device__ float g_hsig[(size_t)M_ROWS * D_HID];   // 75.5 MB
__device__ float g_rowstat1[M_ROWS];
__device__ float g_rowstat2[M_ROWS];
#define NPART1 (D_HID / BN)                       // 36 col-blocks in GEMM1
__device__ float g_part2[NPART1 * M_ROWS];
__device__ float g_ws1[D_HID];
__device__ float g_ws2[D_OUT];
__device__ float g_csq1[8 * D_HID];
__device__ float g_csq2[8 * D_OUT];
__device__ int   g_mask_kind;                     // 0=u8, 1=i32, 2=f32

// ---------------- helpers ----------------
__device__ __forceinline__ float cleanf(float x) {
    if (isnan(x)) return 1e-5f;
    if (isinf(x)) return 1.0f;
    return x;
}

__device__ __forceinline__ float softplusf(float x) {
    return (x > 20.0f) ? x : log1pf(expf(x));
}

__device__ __forceinline__ float fetch_mask(const void* p, size_t i, int kind) {
    if (kind == 2) return ((const float*)p)[i];
    if (kind == 1) return (float)(((const int*)p)[i]);
    return (float)(((const unsigned char*)p)[i]);
}

__device__ __forceinline__ uint32_t smaddr(const void* p) {
    return (uint32_t)__cvta_generic_to_shared(p);
}

__device__ __forceinline__ void cpasync16(uint32_t s, const void* g) {
    asm volatile("cp.async.cg.shared.global [%0], [%1], 16;\n" :: "r"(s), "l"(g));
}

__device__ __forceinline__ uint32_t f2tf(float x) {
    uint32_t u;
    asm("cvt.rna.tf32.f32 %0, %1;" : "=r"(u) : "f"(x));
    return u;
}

__device__ __forceinline__ void mma8(float c[4], const uint32_t a[4], uint32_t b0, uint32_t b1) {
    asm volatile(
        "mma.sync.aligned.m16n8k8.row.col.f32.tf32.tf32.f32 "
        "{%0,%1,%2,%3}, {%4,%5,%6,%7}, {%8,%9}, {%0,%1,%2,%3};\n"
        : "+f"(c[0]), "+f"(c[1]), "+f"(c[2]), "+f"(c[3])
        : "r"(a[0]), "r"(a[1]), "r"(a[2]), "r"(a[3]), "r"(b0), "r"(b1));
}

// ---------------- mask dtype detection ----------------
__global__ void detect_k(const unsigned int* m) {
    if (threadIdx.x != 0) return;
    bool f32ok = true, i32ok = true, any_f = false, any_i = false;
    for (int i = 0; i < 64; ++i) {
        unsigned w = m[i];
        if (w == 0x3F800000u) { any_f = true; i32ok = false; }
        else if (w == 1u)     { any_i = true; f32ok = false; }
        else if (w != 0u)     { f32ok = false; i32ok = false; }
    }
    int kind;
    if (f32ok && any_f)      kind = 2;
    else if (i32ok && any_i) kind = 1;
    else                     kind = 0;
    g_mask_kind = kind;
}

// ---------------- softplus of w_sigma ----------------
__global__ void ws_k(const float* __restrict__ s1, const float* __restrict__ s2) {
    int i = blockIdx.x * 256 + threadIdx.x;
    if (i < D_HID) g_ws1[i] = softplusf(s1[i]);
    if (i < D_OUT) g_ws2[i] = softplusf(s2[i]);
}

// ---------------- column sums of w^2 (K split into 8 chunks, deterministic) ----
template <int L>
__global__ void colsq_k(const float* __restrict__ w) {
    const int N = (L == 1) ? D_HID : D_OUT;
    const int K = (L == 1) ? D_IN : D_HID;
    const int col = blockIdx.x * 128 + threadIdx.x;
    const int kc = K / 8;
    const int kb = blockIdx.y * kc;
    float s = 0.f;
    #pragma unroll 4
    for (int k = kb; k < kb + kc; ++k) {
        float v = w[(size_t)k * N + col];
        s += v * v;
    }
    if (L == 1) g_csq1[blockIdx.y * D_HID + col] = s;
    else        g_csq2[blockIdx.y * D_OUT + col] = s;
}

// ---------------- KL scalar ----------------
__global__ void kl_k(float* __restrict__ out) {
    __shared__ float red[512];
    const int t = threadIdx.x;
    float v = 0.f;
    for (int j = t; j < D_HID; j += 512) {
        float w = g_ws1[j];
        float cs = 0.f;
        #pragma unroll
        for (int c = 0; c < 8; ++c) cs += g_csq1[c * D_HID + j];
        v += (4608.0f * w + cs - 4608.0f - 4608.0f * logf(w)) * (1.0f / (float)D_HID);
    }
    for (int j = t; j < D_OUT; j += 512) {
        float w = g_ws2[j];
        float cs = 0.f;
        #pragma unroll
        for (int c = 0; c < 8; ++c) cs += g_csq2[c * D_OUT + j];
        v += (4608.0f * w + cs - 4608.0f - 4608.0f * logf(w)) * (1.0f / (float)D_OUT);
    }
    red[t] = v;
    __syncthreads();
    for (int s = 256; s; s >>= 1) {
        if (t < s) red[t] += red[t + s];
        __syncthreads();
    }
    if (t == 0) out[0] = 0.5f * red[0];
}

// ---------------- row stats for layer 1: sum(mu^2) + sum(sigma) -------------
__global__ void rowstat1_k(const float* __restrict__ mu, const float* __restrict__ sg) {
    const int w = (blockIdx.x * blockDim.x + threadIdx.x) >> 5;
    const int lane = threadIdx.x & 31;
    if (w >= M_ROWS) return;
    const float4* m4 = (const float4*)(mu + (size_t)w * D_IN);
    const float4* s4 = (const float4*)(sg + (size_t)w * D_IN);
    float s = 0.f;
    for (int i = lane; i < D_IN / 4; i += 32) {
        float4 a = m4[i];
        s += a.x * a.x + a.y * a.y + a.z * a.z + a.w * a.w;
        float4 b = s4[i];
        s += b.x + b.y + b.z + b.w;
    }
    #pragma unroll
    for (int o = 16; o; o >>= 1) s += __shfl_xor_sync(0xffffffffu, s, o);
    if (lane == 0) g_rowstat1[w] = s;
}

// ---------------- reduce GEMM1 per-colblock partials -> rowstat2 -------------
__global__ void rowstat2_k() {
    int r = blockIdx.x * blockDim.x + threadIdx.x;
    if (r < M_ROWS) {
        float s = 0.f;
        #pragma unroll 4
        for (int c = 0; c < NPART1; ++c) s += g_part2[c * M_ROWS + r];
        g_rowstat2[r] = s;
    }
}

// ============================================================================
// Fused dual-accumulator GEMM: acc_mu = Amu@B, acc_sg = Asg@(B*B)
// PHASE 1 epilogue: Sigma assembly + clean + GELU + dropout1 + write hidden +
//                   deterministic per-row partial sums for rowstat2.
// PHASE 2 epilogue: Sigma assembly + clean + dropout2 + final outputs.
// ============================================================================
template <int PHASE>
__global__ void __launch_bounds__(NTHREADS, 1) gemm_fused(
    const float* __restrict__ AmuArg, const float* __restrict__ AsgArg,
    const float* __restrict__ Bw, int K, int N,
    const void* __restrict__ mask,
    float* __restrict__ outMu, float* __restrict__ outSig)
{
    extern __shared__ float sh[];
    const float* Amu = (PHASE == 1) ? AmuArg : g_hmu;
    const float* Asg = (PHASE == 1) ? AsgArg : g_hsig;

    const int tid   = threadIdx.x;
    const int warpId = tid >> 5;
    const int lane  = tid & 31;
    const int warpM = warpId & 3;
    const int warpN = warpId >> 2;
    const int gid   = lane >> 2;
    const int tid4  = lane & 3;
    const int rowBase = blockIdx.y * BM;
    const int colBase = blockIdx.x * BN;

    float accmu[2][4][4];
    float accsg[2][4][4];
    #pragma unroll
    for (int mi = 0; mi < 2; ++mi)
        #pragma unroll
        for (int ni = 0; ni < 4; ++ni)
            #pragma unroll
            for (int j = 0; j < 4; ++j) { accmu[mi][ni][j] = 0.f; accsg[mi][ni][j] = 0.f; }

    const int nK = K / BK;

    auto loadTile = [&](int kt, int s) {
        const int k0 = kt * BK;
        float* sAmu = sh + s * STAGE_F;
        float* sAsg = sAmu + BM * ASTRIDE;
        float* sB   = sAsg + BM * ASTRIDE;
        #pragma unroll
        for (int it = 0; it < 2; ++it) {
            int l = tid + it * NTHREADS;
            int r = l >> 3, c = (l & 7) << 2;
            cpasync16(smaddr(sAmu + r * ASTRIDE + c), Amu + (size_t)(rowBase + r) * K + k0 + c);
            cpasync16(smaddr(sAsg + r * ASTRIDE + c), Asg + (size_t)(rowBase + r) * K + k0 + c);
            int kr = l >> 5, cc = (l & 31) << 2;
            cpasync16(smaddr(sB + kr * BSTRIDE + cc), Bw + (size_t)(k0 + kr) * N + colBase + cc);
        }
        asm volatile("cp.async.commit_group;\n");
    };

    loadTile(0, 0);
    for (int kt = 0; kt < nK; ++kt) {
        const int cur = kt & 1;
        if (kt + 1 < nK) {
            loadTile(kt + 1, cur ^ 1);
            asm volatile("cp.async.wait_group 1;\n");
        } else {
            asm volatile("cp.async.wait_group 0;\n");
        }
        __syncthreads();

        const float* sAmu = sh + cur * STAGE_F;
        const float* sAsg = sAmu + BM * ASTRIDE;
        const float* sB   = sAsg + BM * ASTRIDE;

        #pragma unroll
        for (int ks = 0; ks < 4; ++ks) {
            const int kk = ks * 8;
            uint32_t amu[2][4], asg[2][4];
            #pragma unroll
            for (int mi = 0; mi < 2; ++mi) {
                const float* p = sAmu + (warpM * 32 + mi * 16 + gid) * ASTRIDE + kk + tid4;
                amu[mi][0] = f2tf(p[0]);
                amu[mi][1] = f2tf(p[8 * ASTRIDE]);
                amu[mi][2] = f2tf(p[4]);
                amu[mi][3] = f2tf(p[8 * ASTRIDE + 4]);
                const float* q = sAsg + (warpM * 32 + mi * 16 + gid) * ASTRIDE + kk + tid4;
                asg[mi][0] = f2tf(q[0]);
                asg[mi][1] = f2tf(q[8 * ASTRIDE]);
                asg[mi][2] = f2tf(q[4]);
                asg[mi][3] = f2tf(q[8 * ASTRIDE + 4]);
            }
            #pragma unroll
            for (int ni = 0; ni < 4; ++ni) {
                const float* pb = sB + (kk + tid4) * BSTRIDE + warpN * 32 + ni * 8 + gid;
                float b0f = pb[0];
                float b1f = pb[4 * BSTRIDE];
                uint32_t b0 = f2tf(b0f), b1 = f2tf(b1f);
                uint32_t q0 = f2tf(b0f * b0f), q1 = f2tf(b1f * b1f);
                #pragma unroll
                for (int mi = 0; mi < 2; ++mi) {
                    mma8(accmu[mi][ni], amu[mi], b0, b1);
                    mma8(accsg[mi][ni], asg[mi], q0, q1);
                }
            }
        }
        __syncthreads();
    }

    const int kind = g_mask_kind;

    if (PHASE == 1) {
        // ---- layer-1 epilogue: Sigma + clean + GELU + dropout1 + hidden write
        #pragma unroll
        for (int mi = 0; mi < 2; ++mi) {
            #pragma unroll
            for (int h = 0; h < 2; ++h) {
                const int rloc = warpM * 32 + mi * 16 + h * 8 + gid;
                const int row = rowBase + rloc;
                const float rs = g_rowstat1[row];
                float acc = 0.f;
                #pragma unroll
                for (int ni = 0; ni < 4; ++ni) {
                    const int col = colBase + warpN * 32 + ni * 8 + tid4 * 2;
                    float mu0 = accmu[mi][ni][2 * h];
                    float mu1 = accmu[mi][ni][2 * h + 1];
                    float S0 = cleanf(accsg[mi][ni][2 * h]     + rs * g_ws1[col]);
                    float S1 = cleanf(accsg[mi][ni][2 * h + 1] + rs * g_ws1[col + 1]);
                    float cdf0 = 0.5f * (1.0f + erff(mu0 * 0.70710678118654752f));
                    float gr0  = cdf0 + mu0 * (expf(-0.5f * mu0 * mu0) * 0.3989422804014327f);
                    float cdf1 = 0.5f * (1.0f + erff(mu1 * 0.70710678118654752f));
                    float gr1  = cdf1 + mu1 * (expf(-0.5f * mu1 * mu1) * 0.3989422804014327f);
                    float gm0 = mu0 * cdf0, gm1 = mu1 * cdf1;
                    float gs0 = gr0 * gr0 * S0, gs1 = gr1 * gr1 * S1;
                    size_t idx = (size_t)row * D_HID + col;
                    float m0 = fetch_mask(mask, idx, kind);
                    float m1 = fetch_mask(mask, idx + 1, kind);
                    float hm0 = gm0 * m0 * (1.0f / 0.9f);
                    float hm1 = gm1 * m1 * (1.0f / 0.9f);
                    float hs0 = cleanf(gs0 * m0 * (1.0f / (float)D_HID));
                    float hs1 = cleanf(gs1 * m1 * (1.0f / (float)D_HID));
                    float2 v; v.x = hm0; v.y = hm1;
                    *reinterpret_cast<float2*>(&g_hmu[idx]) = v;
                    float2 w; w.x = hs0; w.y = hs1;
                    *reinterpret_cast<float2*>(&g_hsig[idx]) = w;
                    acc += hm0 * hm0 + hm1 * hm1 + hs0 + hs1;
                }
                acc += __shfl_xor_sync(0xffffffffu, acc, 1);
                acc += __shfl_xor_sync(0xffffffffu, acc, 2);
                if (tid4 == 0) sh[warpN * BM + rloc] = acc;
            }
        }
        __syncthreads();
        if (tid < BM) {
            float s = sh[tid] + sh[BM + tid] + sh[2 * BM + tid] + sh[3 * BM + tid];
            g_part2[(size_t)blockIdx.x * M_ROWS + rowBase + tid] = s;
        }
    } else {
        // ---- layer-2 epilogue: Sigma + clean + dropout2 + final outputs
        #pragma unroll
        for (int mi = 0; mi < 2; ++mi) {
            #pragma unroll
            for (int h = 0; h < 2; ++h) {
                const int row = rowBase + warpM * 32 + mi * 16 + h * 8 + gid;
                const float rs = g_rowstat2[row];
                #pragma unroll
                for (int ni = 0; ni < 4; ++ni) {
                    const int col = colBase + warpN * 32 + ni * 8 + tid4 * 2;
                    float mu0 = accmu[mi][ni][2 * h];
                    float mu1 = accmu[mi][ni][2 * h + 1];
                    float S0 = cleanf(accsg[mi][ni][2 * h]     + rs * g_ws2[col]);
                    float S1 = cleanf(accsg[mi][ni][2 * h + 1] + rs * g_ws2[col + 1]);
                    size_t idx = (size_t)row * D_OUT + col;
                    float m0 = fetch_mask(mask, idx, kind);
                    float m1 = fetch_mask(mask, idx + 1, kind);
                    float o0 = mu0 * m0 * (1.0f / 0.9f);
                    float o1 = mu1 * m1 * (1.0f / 0.9f);
                    float s0 = cleanf(S0 * m0 * (1.0f / (float)D_OUT));
                    float s1 = cleanf(S1 * m1 * (1.0f / (float)D_OUT));
                    float2 v; v.x = o0; v.y = o1;
                    *reinterpret_cast<float2*>(&outMu[idx]) = v;
                    float2 w; w.x = s0; w.y = s1;
                    *reinterpret_cast<float2*>(&outSig[idx]) = w;
                }
            }
        }
    }
}

// ============================================================================
extern "C" void kernel_launch(void* const* d_in, const int* in_sizes, int n_in,
                              void* d_out, int out_size) {
    const float* mu_in  = (const float*)d_in[0];
    const float* sg_in  = (const float*)d_in[1];
    const void*  mask1  = d_in[2];
    const void*  mask2  = d_in[3];
    const float* w1     = (const float*)d_in[4];
    const float* wsig1  = (const float*)d_in[5];
    const float* w2     = (const float*)d_in[6];
    const float* wsig2  = (const float*)d_in[7];
    float* out = (float*)d_out;

    // Output layout: [mu (M*D_OUT)] [sigma (M*D_OUT)] [kl (1)]
    const int half = (out_size - 1) / 2;
    float* out_mu  = out;
    float* out_sig = out + half;
    float* out_kl  = out + (out_size - 1);

    cudaFuncSetAttribute(gemm_fused<1>, cudaFuncAttributeMaxDynamicSharedMemorySize, SMEM_BYTES);
    cudaFuncSetAttribute(gemm_fused<2>, cudaFuncAttributeMaxDynamicSharedMemorySize, SMEM_BYTES);

    detect_k<<<1, 32>>>((const unsigned int*)mask1);
    ws_k<<<(D_HID + 255) / 256, 256>>>(wsig1, wsig2);
    colsq_k<1><<<dim3(D_HID / 128, 8), 128>>>(w1);
    colsq_k<2><<<dim3(D_OUT / 128, 8), 128>>>(w2);
    kl_k<<<1, 512>>>(out_kl);
    rowstat1_k<<<(M_ROWS * 32) / 256, 256>>>(mu_in, sg_in);

    gemm_fused<1><<<dim3(D_HID / BN, M_ROWS / BM), NTHREADS, SMEM_BYTES>>>(
        mu_in, sg_in, w1, D_IN, D_HID, mask1, nullptr, nullptr);

    rowstat2_k<<<M_ROWS / 256, 256>>>();

    gemm_fused<2><<<dim3(D_OUT / BN, M_ROWS / BM), NTHREADS, SMEM_BYTES>>>(
        nullptr, nullptr, w2, D_HID, D_OUT, mask2, out_mu, out_sig);
}

// round 9
// speedup vs baseline: 1.4217x; 1.4217x over previous
#include <cuda_runtime.h>
#include <cuda_fp16.h>
#include <cstdint>
#include <cstddef>
#include <math.h>

// ---------------- problem constants ----------------
#define M_ROWS 4096      // B*N = 8*512
#define D_IN   4608
#define D_HID  4608
#define D_OUT  1152
#define KDIM   4608      // K for BOTH gemms (D_IN == D_HID)

// ---------------- GEMM tiling (fp16 mma.sync.m16n8k16) ----------------
#define BM 128
#define BN 128
#define BK 32
#define NKT (KDIM / BK)             // 144
#define NTHREADS 512
#define GROUP 8                     // supertile height for L2 reuse
#define NPART1 (D_HID / BN)         // 36

#define OFF_AMU 0u
#define OFF_ASG 8192u
#define OFF_B   16384u
#define OFF_BQ  24576u
#define STAGE_B 32768u
#define NSTAGE  4
#define SMEM_ALLOC (NSTAGE * 32768)   // 131072 bytes

// ---------------- device scratch (allocation-free rule) ----------------
__device__ __half g_amuh[(size_t)M_ROWS * D_IN];
__device__ __half g_asgh[(size_t)M_ROWS * D_IN];
__device__ __half g_hmuh[(size_t)M_ROWS * D_HID];
__device__ __half g_hsgh[(size_t)M_ROWS * D_HID];
__device__ __half g_w1h [(size_t)D_IN * D_HID];
__device__ __half g_w1q [(size_t)D_IN * D_HID];
__device__ __half g_w2h [(size_t)D_HID * D_OUT];
__device__ __half g_w2q [(size_t)D_HID * D_OUT];
__device__ float  g_rowstat1[M_ROWS];
__device__ float  g_rowstat2[M_ROWS];
__device__ float  g_part2[NPART1 * M_ROWS];
__device__ float  g_ws1[D_HID];
__device__ float  g_ws2[D_OUT];
__device__ float  g_csq1[8 * D_HID];
__device__ float  g_csq2[8 * D_OUT];
__device__ int    g_mask_kind;       // 0=u8, 1=i32, 2=f32

// ---------------- helpers ----------------
__device__ __forceinline__ float cleanf(float x) {
    if (isnan(x)) return 1e-5f;
    if (isinf(x)) return 1.0f;
    return x;
}
__device__ __forceinline__ float softplusf(float x) {
    return (x > 20.0f) ? x : log1pf(expf(x));
}
__device__ __forceinline__ float fetch_mask(const void* p, size_t i, int kind) {
    if (kind == 2) return ((const float*)p)[i];
    if (kind == 1) return (float)(((const int*)p)[i]);
    return (float)(((const unsigned char*)p)[i]);
}
__device__ __forceinline__ uint32_t smaddr(const void* p) {
    return (uint32_t)__cvta_generic_to_shared(p);
}
__device__ __forceinline__ void cpasync16(uint32_t s, const void* g) {
    asm volatile("cp.async.cg.shared.global [%0], [%1], 16;\n" :: "r"(s), "l"(g));
}
__device__ __forceinline__ void ldsm4(uint32_t r[4], uint32_t a) {
    asm volatile("ldmatrix.sync.aligned.m8n8.x4.shared.b16 {%0,%1,%2,%3}, [%4];"
        : "=r"(r[0]), "=r"(r[1]), "=r"(r[2]), "=r"(r[3]) : "r"(a));
}
__device__ __forceinline__ void ldsm4t(uint32_t r[4], uint32_t a) {
    asm volatile("ldmatrix.sync.aligned.m8n8.x4.trans.shared.b16 {%0,%1,%2,%3}, [%4];"
        : "=r"(r[0]), "=r"(r[1]), "=r"(r[2]), "=r"(r[3]) : "r"(a));
}
__device__ __forceinline__ void mma16816(float c[4], const uint32_t a[4], uint32_t b0, uint32_t b1) {
    asm volatile(
        "mma.sync.aligned.m16n8k16.row.col.f32.f16.f16.f32 "
        "{%0,%1,%2,%3}, {%4,%5,%6,%7}, {%8,%9}, {%0,%1,%2,%3};\n"
        : "+f"(c[0]), "+f"(c[1]), "+f"(c[2]), "+f"(c[3])
        : "r"(a[0]), "r"(a[1]), "r"(a[2]), "r"(a[3]), "r"(b0), "r"(b1));
}

// ---------------- mask dtype detection ----------------
__global__ void detect_k(const unsigned int* m) {
    if (threadIdx.x != 0) return;
    bool f32ok = true, i32ok = true, any_f = false, any_i = false;
    for (int i = 0; i < 64; ++i) {
        unsigned w = m[i];
        if (w == 0x3F800000u) { any_f = true; i32ok = false; }
        else if (w == 1u)     { any_i = true; f32ok = false; }
        else if (w != 0u)     { f32ok = false; i32ok = false; }
    }
    int kind;
    if (f32ok && any_f)      kind = 2;
    else if (i32ok && any_i) kind = 1;
    else                     kind = 0;
    g_mask_kind = kind;
}

// ---------------- softplus of w_sigma ----------------
__global__ void ws_k(const float* __restrict__ s1, const float* __restrict__ s2) {
    int i = blockIdx.x * 256 + threadIdx.x;
    if (i < D_HID) g_ws1[i] = softplusf(s1[i]);
    if (i < D_OUT) g_ws2[i] = softplusf(s2[i]);
}

// ---------------- column sums of w^2 (deterministic 8-chunk split) ----------
template <int L>
__global__ void colsq_k(const float* __restrict__ w) {
    const int N = (L == 1) ? D_HID : D_OUT;
    const int K = (L == 1) ? D_IN : D_HID;
    const int col = blockIdx.x * 128 + threadIdx.x;
    const int kc = K / 8;
    const int kb = blockIdx.y * kc;
    float s = 0.f;
    #pragma unroll 4
    for (int k = kb; k < kb + kc; ++k) {
        float v = w[(size_t)k * N + col];
        s += v * v;
    }
    if (L == 1) g_csq1[blockIdx.y * D_HID + col] = s;
    else        g_csq2[blockIdx.y * D_OUT + col] = s;
}

// ---------------- KL scalar ----------------
__global__ void kl_k(float* __restrict__ out) {
    __shared__ float red[512];
    const int t = threadIdx.x;
    float v = 0.f;
    for (int j = t; j < D_HID; j += 512) {
        float w = g_ws1[j];
        float cs = 0.f;
        #pragma unroll
        for (int c = 0; c < 8; ++c) cs += g_csq1[c * D_HID + j];
        v += (4608.0f * w + cs - 4608.0f - 4608.0f * logf(w)) * (1.0f / (float)D_HID);
    }
    for (int j = t; j < D_OUT; j += 512) {
        float w = g_ws2[j];
        float cs = 0.f;
        #pragma unroll
        for (int c = 0; c < 8; ++c) cs += g_csq2[c * D_OUT + j];
        v += (4608.0f * w + cs - 4608.0f - 4608.0f * logf(w)) * (1.0f / (float)D_OUT);
    }
    red[t] = v;
    __syncthreads();
    for (int s = 256; s; s >>= 1) {
        if (t < s) red[t] += red[t + s];
        __syncthreads();
    }
    if (t == 0) out[0] = 0.5f * red[0];
}

// ---------------- row stats layer1: sum(mu^2)+sum(sigma) (fp32 inputs) ------
__global__ void rowstat1_k(const float* __restrict__ mu, const float* __restrict__ sg) {
    const int w = (blockIdx.x * blockDim.x + threadIdx.x) >> 5;
    const int lane = threadIdx.x & 31;
    if (w >= M_ROWS) return;
    const float4* m4 = (const float4*)(mu + (size_t)w * D_IN);
    const float4* s4 = (const float4*)(sg + (size_t)w * D_IN);
    float s = 0.f;
    for (int i = lane; i < D_IN / 4; i += 32) {
        float4 a = m4[i];
        s += a.x * a.x + a.y * a.y + a.z * a.z + a.w * a.w;
        float4 b = s4[i];
        s += b.x + b.y + b.z + b.w;
    }
    #pragma unroll
    for (int o = 16; o; o >>= 1) s += __shfl_xor_sync(0xffffffffu, s, o);
    if (lane == 0) g_rowstat1[w] = s;
}

// ---------------- reduce GEMM1 partials -> rowstat2 ----------------
__global__ void rowstat2_k() {
    int r = blockIdx.x * blockDim.x + threadIdx.x;
    if (r < M_ROWS) {
        float s = 0.f;
        #pragma unroll 4
        for (int c = 0; c < NPART1; ++c) s += g_part2[c * M_ROWS + r];
        g_rowstat2[r] = s;
    }
}

// ---------------- convert inputs fp32 -> fp16 ----------------
__global__ void conv_in_k(const float* __restrict__ mu, const float* __restrict__ sg) {
    size_t i = ((size_t)blockIdx.x * 256 + threadIdx.x) * 4;
    float4 a = *(const float4*)(mu + i);
    float4 b = *(const float4*)(sg + i);
    *(__half2*)(g_amuh + i)     = __floats2half2_rn(a.x, a.y);
    *(__half2*)(g_amuh + i + 2) = __floats2half2_rn(a.z, a.w);
    *(__half2*)(g_asgh + i)     = __floats2half2_rn(b.x, b.y);
    *(__half2*)(g_asgh + i + 2) = __floats2half2_rn(b.z, b.w);
}

// ---------------- convert weights fp32 -> fp16 (w and w^2) ----------------
template <int L>
__global__ void conv_w_k(const float* __restrict__ w) {
    __half* wh = (L == 1) ? g_w1h : g_w2h;
    __half* wq = (L == 1) ? g_w1q : g_w2q;
    size_t i = ((size_t)blockIdx.x * 256 + threadIdx.x) * 4;
    float4 v = *(const float4*)(w + i);
    *(__half2*)(wh + i)     = __floats2half2_rn(v.x, v.y);
    *(__half2*)(wh + i + 2) = __floats2half2_rn(v.z, v.w);
    *(__half2*)(wq + i)     = __floats2half2_rn(v.x * v.x, v.y * v.y);
    *(__half2*)(wq + i + 2) = __floats2half2_rn(v.z * v.z, v.w * v.w);
}

// ============================================================================
// Dual-accumulator fp16 tensor-core GEMM:
//   acc_mu = Amu @ W,  acc_sg = Asg @ W∘W     (fp32 accumulate)
// A tiles: [128 x 32] fp16, 64B rows, XOR swizzle (c ^ ((r>>1)&3)) -> ldmatrix
// B tiles: [32 x 128] fp16 (original [K,N] layout), 256B rows,
//          XOR swizzle (c ^ (r&7)) -> ldmatrix.trans
// PHASE 1: Sigma + clean + GELU + dropout1 -> fp16 hidden + per-row partials.
// PHASE 2: Sigma + clean + dropout2 -> fp32 outputs.
// ============================================================================
template <int PHASE>
__global__ void __launch_bounds__(NTHREADS, 1) gemm_h(
    const void* __restrict__ mask, float* __restrict__ outMu, float* __restrict__ outSig,
    int tilesN)
{
    extern __shared__ char smem[];
    const uint32_t sbase = smaddr(smem);
    float* shf = (float*)smem;

    const __half* __restrict__ Amu = (PHASE == 1) ? g_amuh : g_hmuh;
    const __half* __restrict__ Asg = (PHASE == 1) ? g_asgh : g_hsgh;
    const __half* __restrict__ Bh  = (PHASE == 1) ? g_w1h : g_w2h;
    const __half* __restrict__ Bq  = (PHASE == 1) ? g_w1q : g_w2q;
    const float* __restrict__ ws   = (PHASE == 1) ? g_ws1 : g_ws2;
    const int HN = (PHASE == 1) ? D_HID : D_OUT;

    const int tid   = threadIdx.x;
    const int warpId = tid >> 5;
    const int lane  = tid & 31;
    const int warpM = warpId & 3;
    const int warpN = warpId >> 2;
    const int gid   = lane >> 2;
    const int tid4  = lane & 3;

    // supertile rasterization for L2 reuse
    const int per = GROUP * tilesN;
    const int gi = blockIdx.x / per, rr = blockIdx.x % per;
    const int tm = gi * GROUP + (rr % GROUP);
    const int tn = rr / GROUP;
    const int rowBase = tm * BM;
    const int colBase = tn * BN;

    float accmu[2][4][4];
    float accsg[2][4][4];
    #pragma unroll
    for (int mi = 0; mi < 2; ++mi)
        #pragma unroll
        for (int ni = 0; ni < 4; ++ni)
            #pragma unroll
            for (int j = 0; j < 4; ++j) { accmu[mi][ni][j] = 0.f; accsg[mi][ni][j] = 0.f; }

    auto load_tile = [&](int t) {
        const uint32_t sb = sbase + (uint32_t)(t & 3) * STAGE_B;
        const int k0 = t * BK;
        {   // A tiles: 128 rows x 4 chunks (16B)
            int r = tid >> 2, c = tid & 3;
            uint32_t sa = sb + (uint32_t)(r * 64 + ((c ^ ((r >> 1) & 3)) << 4));
            const size_t g = (size_t)(rowBase + r) * KDIM + k0 + c * 8;
            cpasync16(sa + OFF_AMU, Amu + g);
            cpasync16(sa + OFF_ASG, Asg + g);
        }
        {   // B tiles: 32 rows x 16 chunks (16B)
            int r = tid >> 4, c = tid & 15;
            uint32_t sa = sb + (uint32_t)(r * 256 + ((c ^ (r & 7)) << 4));
            const size_t g = (size_t)(k0 + r) * HN + colBase + c * 8;
            cpasync16(sa + OFF_B, Bh + g);
            cpasync16(sa + OFF_BQ, Bq + g);
        }
        asm volatile("cp.async.commit_group;\n" ::: "memory");
    };

    load_tile(0); load_tile(1); load_tile(2);

    for (int t = 0; t < NKT; ++t) {
        const int rem = NKT - 1 - t;
        if (rem >= 2)      asm volatile("cp.async.wait_group 2;\n" ::: "memory");
        else if (rem == 1) asm volatile("cp.async.wait_group 1;\n" ::: "memory");
        else               asm volatile("cp.async.wait_group 0;\n" ::: "memory");
        __syncthreads();
        if (t + 3 < NKT) load_tile(t + 3);   // safe: barrier above proves stage free

        const uint32_t sb = sbase + (uint32_t)(t & 3) * STAGE_B;
        #pragma unroll
        for (int ks = 0; ks < 2; ++ks) {
            uint32_t amu[2][4], asg[2][4];
            #pragma unroll
            for (int mi = 0; mi < 2; ++mi) {
                int r = warpM * 32 + mi * 16 + (lane & 15);
                int c = ks * 2 + (lane >> 4);
                uint32_t ad = sb + (uint32_t)(r * 64 + ((c ^ ((r >> 1) & 3)) << 4));
                ldsm4(amu[mi], ad + OFF_AMU);
                ldsm4(asg[mi], ad + OFF_ASG);
            }
            #pragma unroll
            for (int np = 0; np < 2; ++np) {
                int r = ks * 16 + (lane & 15);
                int c = ((warpN * 32 + np * 16) >> 3) + (lane >> 4);
                uint32_t ad = sb + (uint32_t)(r * 256 + ((c ^ (r & 7)) << 4));
                uint32_t bb[4], bqq[4];
                ldsm4t(bb, ad + OFF_B);
                ldsm4t(bqq, ad + OFF_BQ);
                #pragma unroll
                for (int mi = 0; mi < 2; ++mi)
                    #pragma unroll
                    for (int j = 0; j < 2; ++j) {
                        mma16816(accmu[mi][np * 2 + j], amu[mi], bb[2 * j], bb[2 * j + 1]);
                        mma16816(accsg[mi][np * 2 + j], asg[mi], bqq[2 * j], bqq[2 * j + 1]);
                    }
            }
        }
    }
    __syncthreads();

    const int kind = g_mask_kind;

    if (PHASE == 1) {
        // ---- layer-1 epilogue: Sigma + clean + GELU + dropout1 -> fp16 hidden
        #pragma unroll
        for (int mi = 0; mi < 2; ++mi) {
            #pragma unroll
            for (int h = 0; h < 2; ++h) {
                const int rloc = warpM * 32 + mi * 16 + h * 8 + gid;
                const int row = rowBase + rloc;
                const float rs = g_rowstat1[row];
                float acc = 0.f;
                #pragma unroll
                for (int ni = 0; ni < 4; ++ni) {
                    const int col = colBase + warpN * 32 + ni * 8 + tid4 * 2;
                    float mu0 = accmu[mi][ni][2 * h];
                    float mu1 = accmu[mi][ni][2 * h + 1];
                    float S0 = cleanf(accsg[mi][ni][2 * h]     + rs * ws[col]);
                    float S1 = cleanf(accsg[mi][ni][2 * h + 1] + rs * ws[col + 1]);
                    float cdf0 = 0.5f * (1.0f + erff(mu0 * 0.70710678118654752f));
                    float gr0  = cdf0 + mu0 * (expf(-0.5f * mu0 * mu0) * 0.3989422804014327f);
                    float cdf1 = 0.5f * (1.0f + erff(mu1 * 0.70710678118654752f));
                    float gr1  = cdf1 + mu1 * (expf(-0.5f * mu1 * mu1) * 0.3989422804014327f);
                    float gm0 = mu0 * cdf0, gm1 = mu1 * cdf1;
                    float gs0 = gr0 * gr0 * S0, gs1 = gr1 * gr1 * S1;
                    size_t idx = (size_t)row * D_HID + col;
                    float m0 = fetch_mask(mask, idx, kind);
                    float m1 = fetch_mask(mask, idx + 1, kind);
                    float hm0 = gm0 * m0 * (1.0f / 0.9f);
                    float hm1 = gm1 * m1 * (1.0f / 0.9f);
                    float hs0 = cleanf(gs0 * m0 * (1.0f / (float)D_HID));
                    float hs1 = cleanf(gs1 * m1 * (1.0f / (float)D_HID));
                    __half2 hm2 = __floats2half2_rn(hm0, hm1);
                    __half2 hs2 = __floats2half2_rn(hs0, hs1);
                    *(__half2*)(g_hmuh + idx) = hm2;
                    *(__half2*)(g_hsgh + idx) = hs2;
                    // use fp16-rounded values so rowstat2 matches GEMM2's operands
                    float rm0 = __low2float(hm2), rm1 = __high2float(hm2);
                    float rs0 = __low2float(hs2), rs1 = __high2float(hs2);
                    acc += rm0 * rm0 + rm1 * rm1 + rs0 + rs1;
                }
                acc += __shfl_xor_sync(0xffffffffu, acc, 1);
                acc += __shfl_xor_sync(0xffffffffu, acc, 2);
                if (tid4 == 0) shf[warpN * BM + rloc] = acc;
            }
        }
        __syncthreads();
        if (tid < BM) {
            float s = shf[tid] + shf[BM + tid] + shf[2 * BM + tid] + shf[3 * BM + tid];
            g_part2[(size_t)tn * M_ROWS + rowBase + tid] = s;
        }
    } else {
        // ---- layer-2 epilogue: Sigma + clean + dropout2 -> fp32 outputs
        #pragma unroll
        for (int mi = 0; mi < 2; ++mi) {
            #pragma unroll
            for (int h = 0; h < 2; ++h) {
                const int row = rowBase + warpM * 32 + mi * 16 + h * 8 + gid;
                const float rs = g_rowstat2[row];
                #pragma unroll
                for (int ni = 0; ni < 4; ++ni) {
                    const int col = colBase + warpN * 32 + ni * 8 + tid4 * 2;
                    float mu0 = accmu[mi][ni][2 * h];
                    float mu1 = accmu[mi][ni][2 * h + 1];
                    float S0 = cleanf(accsg[mi][ni][2 * h]     + rs * ws[col]);
                    float S1 = cleanf(accsg[mi][ni][2 * h + 1] + rs * ws[col + 1]);
                    size_t idx = (size_t)row * D_OUT + col;
                    float m0 = fetch_mask(mask, idx, kind);
                    float m1 = fetch_mask(mask, idx + 1, kind);
                    float2 v;
                    v.x = mu0 * m0 * (1.0f / 0.9f);
                    v.y = mu1 * m1 * (1.0f / 0.9f);
                    float2 w;
                    w.x = cleanf(S0 * m0 * (1.0f / (float)D_OUT));
                    w.y = cleanf(S1 * m1 * (1.0f / (float)D_OUT));
                    *reinterpret_cast<float2*>(&outMu[idx]) = v;
                    *reinterpret_cast<float2*>(&outSig[idx]) = w;
                }
            }
        }
    }
}

// ============================================================================
extern "C" void kernel_launch(void* const* d_in, const int* in_sizes, int n_in,
                              void* d_out, int out_size) {
    const float* mu_in  = (const float*)d_in[0];
    const float* sg_in  = (const float*)d_in[1];
    const void*  mask1  = d_in[2];
    const void*  mask2  = d_in[3];
    const float* w1     = (const float*)d_in[4];
    const float* wsig1  = (const float*)d_in[5];
    const float* w2     = (const float*)d_in[6];
    const float* wsig2  = (const float*)d_in[7];
    float* out = (float*)d_out;

    // Output layout: [mu (M*D_OUT)] [sigma (M*D_OUT)] [kl (1)]
    const int half = (out_size - 1) / 2;
    float* out_mu  = out;
    float* out_sig = out + half;
    float* out_kl  = out + (out_size - 1);

    cudaFuncSetAttribute(gemm_h<1>, cudaFuncAttributeMaxDynamicSharedMemorySize, SMEM_ALLOC);
    cudaFuncSetAttribute(gemm_h<2>, cudaFuncAttributeMaxDynamicSharedMemorySize, SMEM_ALLOC);

    detect_k<<<1, 32>>>((const unsigned int*)mask1);
    ws_k<<<(D_HID + 255) / 256, 256>>>(wsig1, wsig2);
    colsq_k<1><<<dim3(D_HID / 128, 8), 128>>>(w1);
    colsq_k<2><<<dim3(D_OUT / 128, 8), 128>>>(w2);
    kl_k<<<1, 512>>>(out_kl);
    rowstat1_k<<<(M_ROWS * 32) / 256, 256>>>(mu_in, sg_in);
    conv_in_k<<<(int)(((size_t)M_ROWS * D_IN / 4) / 256), 256>>>(mu_in, sg_in);
    conv_w_k<1><<<(int)(((size_t)D_IN * D_HID / 4) / 256), 256>>>(w1);
    conv_w_k<2><<<(int)(((size_t)D_HID * D_OUT / 4) / 256), 256>>>(w2);

    gemm_h<1><<<(M_ROWS / BM) * (D_HID / BN), NTHREADS, SMEM_ALLOC>>>(
        mask1, nullptr, nullptr, D_HID / BN);

    rowstat2_k<<<M_ROWS / 256, 256>>>();

    gemm_h<2><<<(M_ROWS / BM) * (D_OUT / BN), NTHREADS, SMEM_ALLOC>>>(
        mask2, out_mu, out_sig, D_OUT / BN);
}

// round 10
// speedup vs baseline: 2.7277x; 1.9185x over previous
#include <cuda_runtime.h>
#include <cuda_fp16.h>
#include <cstdint>
#include <cstddef>
#include <math.h>

// ---------------- problem constants ----------------
#define M_ROWS 4096      // B*N = 8*512
#define D_IN   4608
#define D_HID  4608
#define D_OUT  1152
#define KDIM   4608      // K for BOTH gemms (D_IN == D_HID)

// ---------------- GEMM tiling (fp16 mma.sync.m16n8k16) ----------------
#define BM 128
#define BN 128
#define BK 64
#define NKT (KDIM / BK)             // 72
#define NTHREADS 512
#define GROUP 8                     // supertile height for L2 reuse
#define NPART1 (D_HID / BN)         // 36
#define NCH 32                      // colsq K-chunks

#define OFF_AMU 0u
#define OFF_ASG 16384u
#define OFF_B   32768u
#define STAGE_B 49152u
#define NSTAGE  4
#define SMEM_ALLOC (NSTAGE * 49152)   // 196608 bytes

// ---------------- device scratch (allocation-free rule) ----------------
__device__ __half g_amuh[(size_t)M_ROWS * D_IN];
__device__ __half g_asgh[(size_t)M_ROWS * D_IN];
__device__ __half g_hmuh[(size_t)M_ROWS * D_HID];
__device__ __half g_hsgh[(size_t)M_ROWS * D_HID];
__device__ __half g_w1h [(size_t)D_IN * D_HID];
__device__ __half g_w2h [(size_t)D_HID * D_OUT];
__device__ float  g_rowstat1[M_ROWS];
__device__ float  g_rowstat2[M_ROWS];
__device__ float  g_part2[NPART1 * M_ROWS];
__device__ float  g_ws1[D_HID];
__device__ float  g_ws2[D_OUT];
__device__ float  g_csq1[NCH * D_HID];
__device__ float  g_csq2[NCH * D_OUT];
__device__ int    g_mask_kind;       // 0=u8, 1=i32, 2=f32

// ---------------- helpers ----------------
__device__ __forceinline__ float cleanf(float x) {
    if (isnan(x)) return 1e-5f;
    if (isinf(x)) return 1.0f;
    return x;
}
__device__ __forceinline__ float softplusf(float x) {
    return (x > 20.0f) ? x : log1pf(expf(x));
}
__device__ __forceinline__ float fetch_mask(const void* p, size_t i, int kind) {
    if (kind == 2) return ((const float*)p)[i];
    if (kind == 1) return (float)(((const int*)p)[i]);
    return (float)(((const unsigned char*)p)[i]);
}
__device__ __forceinline__ uint32_t smaddr(const void* p) {
    return (uint32_t)__cvta_generic_to_shared(p);
}
__device__ __forceinline__ void cpasync16(uint32_t s, const void* g) {
    asm volatile("cp.async.cg.shared.global [%0], [%1], 16;\n" :: "r"(s), "l"(g));
}
__device__ __forceinline__ void ldsm4(uint32_t r[4], uint32_t a) {
    asm volatile("ldmatrix.sync.aligned.m8n8.x4.shared.b16 {%0,%1,%2,%3}, [%4];"
        : "=r"(r[0]), "=r"(r[1]), "=r"(r[2]), "=r"(r[3]) : "r"(a));
}
__device__ __forceinline__ void ldsm4t(uint32_t r[4], uint32_t a) {
    asm volatile("ldmatrix.sync.aligned.m8n8.x4.trans.shared.b16 {%0,%1,%2,%3}, [%4];"
        : "=r"(r[0]), "=r"(r[1]), "=r"(r[2]), "=r"(r[3]) : "r"(a));
}
__device__ __forceinline__ void mma16816(float c[4], const uint32_t a[4], uint32_t b0, uint32_t b1) {
    asm volatile(
        "mma.sync.aligned.m16n8k16.row.col.f32.f16.f16.f32 "
        "{%0,%1,%2,%3}, {%4,%5,%6,%7}, {%8,%9}, {%0,%1,%2,%3};\n"
        : "+f"(c[0]), "+f"(c[1]), "+f"(c[2]), "+f"(c[3])
        : "r"(a[0]), "r"(a[1]), "r"(a[2]), "r"(a[3]), "r"(b0), "r"(b1));
}
__device__ __forceinline__ uint32_t hsq2(uint32_t b) {   // fp16x2 elementwise square
    __half2 h = *reinterpret_cast<__half2*>(&b);
    h = __hmul2(h, h);
    return *reinterpret_cast<uint32_t*>(&h);
}

// ---------------- mask dtype detection ----------------
__global__ void detect_k(const unsigned int* m) {
    if (threadIdx.x != 0) return;
    bool f32ok = true, i32ok = true, any_f = false, any_i = false;
    for (int i = 0; i < 64; ++i) {
        unsigned w = m[i];
        if (w == 0x3F800000u) { any_f = true; i32ok = false; }
        else if (w == 1u)     { any_i = true; f32ok = false; }
        else if (w != 0u)     { f32ok = false; i32ok = false; }
    }
    int kind;
    if (f32ok && any_f)      kind = 2;
    else if (i32ok && any_i) kind = 1;
    else                     kind = 0;
    g_mask_kind = kind;
}

// ---------------- softplus of w_sigma ----------------
__global__ void ws_k(const float* __restrict__ s1, const float* __restrict__ s2) {
    int i = blockIdx.x * 256 + threadIdx.x;
    if (i < D_HID) g_ws1[i] = softplusf(s1[i]);
    if (i < D_OUT) g_ws2[i] = softplusf(s2[i]);
}

// ---------------- column sums of w^2 (deterministic NCH-chunk split) --------
template <int L>
__global__ void colsq_k(const float* __restrict__ w) {
    const int N = (L == 1) ? D_HID : D_OUT;
    const int K = (L == 1) ? D_IN : D_HID;
    const int col = blockIdx.x * 128 + threadIdx.x;
    const int kc = K / NCH;
    const int kb = blockIdx.y * kc;
    float s = 0.f;
    #pragma unroll 4
    for (int k = kb; k < kb + kc; ++k) {
        float v = w[(size_t)k * N + col];
        s += v * v;
    }
    if (L == 1) g_csq1[blockIdx.y * D_HID + col] = s;
    else        g_csq2[blockIdx.y * D_OUT + col] = s;
}

// ---------------- KL scalar ----------------
__global__ void kl_k(float* __restrict__ out) {
    __shared__ float red[512];
    const int t = threadIdx.x;
    float v = 0.f;
    for (int j = t; j < D_HID; j += 512) {
        float w = g_ws1[j];
        float cs = 0.f;
        #pragma unroll
        for (int c = 0; c < NCH; ++c) cs += g_csq1[c * D_HID + j];
        v += (4608.0f * w + cs - 4608.0f - 4608.0f * logf(w)) * (1.0f / (float)D_HID);
    }
    for (int j = t; j < D_OUT; j += 512) {
        float w = g_ws2[j];
        float cs = 0.f;
        #pragma unroll
        for (int c = 0; c < NCH; ++c) cs += g_csq2[c * D_OUT + j];
        v += (4608.0f * w + cs - 4608.0f - 4608.0f * logf(w)) * (1.0f / (float)D_OUT);
    }
    red[t] = v;
    __syncthreads();
    for (int s = 256; s; s >>= 1) {
        if (t < s) red[t] += red[t + s];
        __syncthreads();
    }
    if (t == 0) out[0] = 0.5f * red[0];
}

// ---------------- fused: rowstat1 + fp32->fp16 input conversion -------------
// one warp per row: computes sum(mu^2)+sum(sigma) AND writes fp16 copies.
__global__ void rowstat1_conv_k(const float* __restrict__ mu, const float* __restrict__ sg) {
    const int w = (blockIdx.x * blockDim.x + threadIdx.x) >> 5;
    const int lane = threadIdx.x & 31;
    if (w >= M_ROWS) return;
    const size_t base = (size_t)w * D_IN;
    const float4* m4 = (const float4*)(mu + base);
    const float4* s4 = (const float4*)(sg + base);
    float s = 0.f;
    for (int i = lane; i < D_IN / 4; i += 32) {
        float4 a = m4[i];
        s += a.x * a.x + a.y * a.y + a.z * a.z + a.w * a.w;
        float4 b = s4[i];
        s += b.x + b.y + b.z + b.w;
        const size_t g = base + (size_t)i * 4;
        *(__half2*)(g_amuh + g)     = __floats2half2_rn(a.x, a.y);
        *(__half2*)(g_amuh + g + 2) = __floats2half2_rn(a.z, a.w);
        *(__half2*)(g_asgh + g)     = __floats2half2_rn(b.x, b.y);
        *(__half2*)(g_asgh + g + 2) = __floats2half2_rn(b.z, b.w);
    }
    #pragma unroll
    for (int o = 16; o; o >>= 1) s += __shfl_xor_sync(0xffffffffu, s, o);
    if (lane == 0) g_rowstat1[w] = s;
}

// ---------------- reduce GEMM1 partials -> rowstat2 ----------------
__global__ void rowstat2_k() {
    int r = blockIdx.x * blockDim.x + threadIdx.x;
    if (r < M_ROWS) {
        float s = 0.f;
        #pragma unroll 4
        for (int c = 0; c < NPART1; ++c) s += g_part2[c * M_ROWS + r];
        g_rowstat2[r] = s;
    }
}

// ---------------- convert weights fp32 -> fp16 ----------------
template <int L>
__global__ void conv_w_k(const float* __restrict__ w) {
    __half* wh = (L == 1) ? g_w1h : g_w2h;
    size_t i = ((size_t)blockIdx.x * 256 + threadIdx.x) * 4;
    float4 v = *(const float4*)(w + i);
    *(__half2*)(wh + i)     = __floats2half2_rn(v.x, v.y);
    *(__half2*)(wh + i + 2) = __floats2half2_rn(v.z, v.w);
}

// ============================================================================
// Dual-accumulator fp16 tensor-core GEMM:
//   acc_mu = Amu @ W,  acc_sg = Asg @ (W∘W)   (fp32 accumulate)
// W∘W fragments derived IN REGISTERS from W fragments via __hmul2 — no second
// B operand in smem or gmem.
// A tiles: [128 x 64] fp16, 128B rows, XOR swizzle (c ^ (r&7)), c in 0..7
// B tiles: [64 x 128] fp16 ([K,N] layout), 256B rows, XOR swizzle (c ^ (r&7))
// PHASE 1: Sigma + clean + GELU + dropout1 -> fp16 hidden + per-row partials.
// PHASE 2: Sigma + clean + dropout2 -> fp32 outputs.
// ============================================================================
template <int PHASE>
__global__ void __launch_bounds__(NTHREADS, 1) gemm_h(
    const void* __restrict__ mask, float* __restrict__ outMu, float* __restrict__ outSig,
    int tilesN)
{
    extern __shared__ char smem[];
    const uint32_t sbase = smaddr(smem);
    float* shf = (float*)smem;

    const __half* __restrict__ Amu = (PHASE == 1) ? g_amuh : g_hmuh;
    const __half* __restrict__ Asg = (PHASE == 1) ? g_asgh : g_hsgh;
    const __half* __restrict__ Bh  = (PHASE == 1) ? g_w1h : g_w2h;
    const float* __restrict__ ws   = (PHASE == 1) ? g_ws1 : g_ws2;
    const int HN = (PHASE == 1) ? D_HID : D_OUT;

    const int tid   = threadIdx.x;
    const int warpId = tid >> 5;
    const int lane  = tid & 31;
    const int warpM = warpId & 3;
    const int warpN = warpId >> 2;
    const int gid   = lane >> 2;
    const int tid4  = lane & 3;

    // supertile rasterization for L2 reuse
    const int per = GROUP * tilesN;
    const int gi = blockIdx.x / per, rr = blockIdx.x % per;
    const int tm = gi * GROUP + (rr % GROUP);
    const int tn = rr / GROUP;
    const int rowBase = tm * BM;
    const int colBase = tn * BN;

    float accmu[2][4][4];
    float accsg[2][4][4];
    #pragma unroll
    for (int mi = 0; mi < 2; ++mi)
        #pragma unroll
        for (int ni = 0; ni < 4; ++ni)
            #pragma unroll
            for (int j = 0; j < 4; ++j) { accmu[mi][ni][j] = 0.f; accsg[mi][ni][j] = 0.f; }

    auto load_tile = [&](int t) {
        const uint32_t sb = sbase + (uint32_t)(t & (NSTAGE - 1)) * STAGE_B;
        const int k0 = t * BK;
        {   // A tiles: 128 rows x 8 chunks (16B) = 1024 chunks, 2 per thread
            #pragma unroll
            for (int it = 0; it < 2; ++it) {
                int id = tid + it * NTHREADS;
                int r = id >> 3, c = id & 7;
                uint32_t sa = sb + (uint32_t)(r * 128 + ((c ^ (r & 7)) << 4));
                const size_t g = (size_t)(rowBase + r) * KDIM + k0 + c * 8;
                cpasync16(sa + OFF_AMU, Amu + g);
                cpasync16(sa + OFF_ASG, Asg + g);
            }
        }
        {   // B tile: 64 rows x 16 chunks (16B) = 1024 chunks, 2 per thread
            #pragma unroll
            for (int it = 0; it < 2; ++it) {
                int id = tid + it * NTHREADS;
                int r = id >> 4, c = id & 15;
                uint32_t sa = sb + (uint32_t)(r * 256 + ((c ^ (r & 7)) << 4));
                cpasync16(sa + OFF_B, Bh + (size_t)(k0 + r) * HN + colBase + c * 8);
            }
        }
        asm volatile("cp.async.commit_group;\n" ::: "memory");
    };

    load_tile(0); load_tile(1); load_tile(2);

    for (int t = 0; t < NKT; ++t) {
        const int rem = NKT - 1 - t;
        if (rem >= 2)      asm volatile("cp.async.wait_group 2;\n" ::: "memory");
        else if (rem == 1) asm volatile("cp.async.wait_group 1;\n" ::: "memory");
        else               asm volatile("cp.async.wait_group 0;\n" ::: "memory");
        __syncthreads();
        if (t + 3 < NKT) load_tile(t + 3);   // safe: barrier above proves stage free

        const uint32_t sb = sbase + (uint32_t)(t & (NSTAGE - 1)) * STAGE_B;
        #pragma unroll
        for (int ks = 0; ks < 4; ++ks) {
            uint32_t amu[2][4], asg[2][4];
            #pragma unroll
            for (int mi = 0; mi < 2; ++mi) {
                int r = warpM * 32 + mi * 16 + (lane & 15);
                int c = ks * 2 + (lane >> 4);
                uint32_t ad = sb + (uint32_t)(r * 128 + ((c ^ (r & 7)) << 4));
                ldsm4(amu[mi], ad + OFF_AMU);
                ldsm4(asg[mi], ad + OFF_ASG);
            }
            #pragma unroll
            for (int np = 0; np < 2; ++np) {
                int r = ks * 16 + (lane & 15);
                int c = warpN * 4 + np * 2 + (lane >> 4);
                uint32_t ad = sb + (uint32_t)(r * 256 + ((c ^ (r & 7)) << 4));
                uint32_t bb[4];
                ldsm4t(bb, ad + OFF_B);
                uint32_t bq0 = hsq2(bb[0]), bq1 = hsq2(bb[1]);
                uint32_t bq2 = hsq2(bb[2]), bq3 = hsq2(bb[3]);
                #pragma unroll
                for (int mi = 0; mi < 2; ++mi) {
                    mma16816(accmu[mi][np * 2 + 0], amu[mi], bb[0], bb[1]);
                    mma16816(accmu[mi][np * 2 + 1], amu[mi], bb[2], bb[3]);
                    mma16816(accsg[mi][np * 2 + 0], asg[mi], bq0, bq1);
                    mma16816(accsg[mi][np * 2 + 1], asg[mi], bq2, bq3);
                }
            }
        }
    }
    __syncthreads();

    const int kind = g_mask_kind;

    if (PHASE == 1) {
        // ---- layer-1 epilogue: Sigma + clean + GELU + dropout1 -> fp16 hidden
        #pragma unroll
        for (int mi = 0; mi < 2; ++mi) {
            #pragma unroll
            for (int h = 0; h < 2; ++h) {
                const int rloc = warpM * 32 + mi * 16 + h * 8 + gid;
                const int row = rowBase + rloc;
                const float rs = g_rowstat1[row];
                float acc = 0.f;
                #pragma unroll
                for (int ni = 0; ni < 4; ++ni) {
                    const int col = colBase + warpN * 32 + ni * 8 + tid4 * 2;
                    float mu0 = accmu[mi][ni][2 * h];
                    float mu1 = accmu[mi][ni][2 * h + 1];
                    float S0 = cleanf(accsg[mi][ni][2 * h]     + rs * ws[col]);
                    float S1 = cleanf(accsg[mi][ni][2 * h + 1] + rs * ws[col + 1]);
                    float cdf0 = 0.5f * (1.0f + erff(mu0 * 0.70710678118654752f));
                    float gr0  = cdf0 + mu0 * (expf(-0.5f * mu0 * mu0) * 0.3989422804014327f);
                    float cdf1 = 0.5f * (1.0f + erff(mu1 * 0.70710678118654752f));
                    float gr1  = cdf1 + mu1 * (expf(-0.5f * mu1 * mu1) * 0.3989422804014327f);
                    float gm0 = mu0 * cdf0, gm1 = mu1 * cdf1;
                    float gs0 = gr0 * gr0 * S0, gs1 = gr1 * gr1 * S1;
                    size_t idx = (size_t)row * D_HID + col;
                    float m0 = fetch_mask(mask, idx, kind);
                    float m1 = fetch_mask(mask, idx + 1, kind);
                    float hm0 = gm0 * m0 * (1.0f / 0.9f);
                    float hm1 = gm1 * m1 * (1.0f / 0.9f);
                    float hs0 = cleanf(gs0 * m0 * (1.0f / (float)D_HID));
                    float hs1 = cleanf(gs1 * m1 * (1.0f / (float)D_HID));
                    __half2 hm2 = __floats2half2_rn(hm0, hm1);
                    __half2 hs2 = __floats2half2_rn(hs0, hs1);
                    *(__half2*)(g_hmuh + idx) = hm2;
                    *(__half2*)(g_hsgh + idx) = hs2;
                    // fp16-rounded values so rowstat2 matches GEMM2's operands
                    float rm0 = __low2float(hm2), rm1 = __high2float(hm2);
                    float rs0 = __low2float(hs2), rs1 = __high2float(hs2);
                    acc += rm0 * rm0 + rm1 * rm1 + rs0 + rs1;
                }
                acc += __shfl_xor_sync(0xffffffffu, acc, 1);
                acc += __shfl_xor_sync(0xffffffffu, acc, 2);
                if (tid4 == 0) shf[warpN * BM + rloc] = acc;
            }
        }
        __syncthreads();
        if (tid < BM) {
            float s = shf[tid] + shf[BM + tid] + shf[2 * BM + tid] + shf[3 * BM + tid];
            g_part2[(size_t)tn * M_ROWS + rowBase + tid] = s;
        }
    } else {
        // ---- layer-2 epilogue: Sigma + clean + dropout2 -> fp32 outputs
        #pragma unroll
        for (int mi = 0; mi < 2; ++mi) {
            #pragma unroll
            for (int h = 0; h < 2; ++h) {
                const int row = rowBase + warpM * 32 + mi * 16 + h * 8 + gid;
                const float rs = g_rowstat2[row];
                #pragma unroll
                for (int ni = 0; ni < 4; ++ni) {
                    const int col = colBase + warpN * 32 + ni * 8 + tid4 * 2;
                    float mu0 = accmu[mi][ni][2 * h];
                    float mu1 = accmu[mi][ni][2 * h + 1];
                    float S0 = cleanf(accsg[mi][ni][2 * h]     + rs * ws[col]);
                    float S1 = cleanf(accsg[mi][ni][2 * h + 1] + rs * ws[col + 1]);
                    size_t idx = (size_t)row * D_OUT + col;
                    float m0 = fetch_mask(mask, idx, kind);
                    float m1 = fetch_mask(mask, idx + 1, kind);
                    float2 v;
                    v.x = mu0 * m0 * (1.0f / 0.9f);
                    v.y = mu1 * m1 * (1.0f / 0.9f);
                    float2 w;
                    w.x = cleanf(S0 * m0 * (1.0f / (float)D_OUT));
                    w.y = cleanf(S1 * m1 * (1.0f / (float)D_OUT));
                    *reinterpret_cast<float2*>(&outMu[idx]) = v;
                    *reinterpret_cast<float2*>(&outSig[idx]) = w;
                }
            }
        }
    }
}

// ============================================================================
extern "C" void kernel_launch(void* const* d_in, const int* in_sizes, int n_in,
                              void* d_out, int out_size) {
    const float* mu_in  = (const float*)d_in[0];
    const float* sg_in  = (const float*)d_in[1];
    const void*  mask1  = d_in[2];
    const void*  mask2  = d_in[3];
    const float* w1     = (const float*)d_in[4];
    const float* wsig1  = (const float*)d_in[5];
    const float* w2     = (const float*)d_in[6];
    const float* wsig2  = (const float*)d_in[7];
    float* out = (float*)d_out;

    // Output layout: [mu (M*D_OUT)] [sigma (M*D_OUT)] [kl (1)]
    const int half = (out_size - 1) / 2;
    float* out_mu  = out;
    float* out_sig = out + half;
    float* out_kl  = out + (out_size - 1);

    cudaFuncSetAttribute(gemm_h<1>, cudaFuncAttributeMaxDynamicSharedMemorySize, SMEM_ALLOC);
    cudaFuncSetAttribute(gemm_h<2>, cudaFuncAttributeMaxDynamicSharedMemorySize, SMEM_ALLOC);

    detect_k<<<1, 32>>>((const unsigned int*)mask1);
    ws_k<<<(D_HID + 255) / 256, 256>>>(wsig1, wsig2);
    colsq_k<1><<<dim3(D_HID / 128, NCH), 128>>>(w1);
    colsq_k<2><<<dim3(D_OUT / 128, NCH), 128>>>(w2);
    kl_k<<<1, 512>>>(out_kl);
    rowstat1_conv_k<<<(M_ROWS * 32) / 256, 256>>>(mu_in, sg_in);
    conv_w_k<1><<<(int)(((size_t)D_IN * D_HID / 4) / 256), 256>>>(w1);
    conv_w_k<2><<<(int)(((size_t)D_HID * D_OUT / 4) / 256), 256>>>(w2);

    gemm_h<1><<<(M_ROWS / BM) * (D_HID / BN), NTHREADS, SMEM_ALLOC>>>(
        mask1, nullptr, nullptr, D_HID / BN);

    rowstat2_k<<<M_ROWS / 256, 256>>>();

    gemm_h<2><<<(M_ROWS / BM) * (D_OUT / BN), NTHREADS, SMEM_ALLOC>>>(
        mask2, out_mu, out_sig, D_OUT / BN);
}

// round 11
// speedup vs baseline: 2.8975x; 1.0623x over previous
#include <cuda_runtime.h>
#include <cuda_fp16.h>
#include <cstdint>
#include <cstddef>
#include <math.h>

// ---------------- problem constants ----------------
#define M_ROWS 4096      // B*N = 8*512
#define D_IN   4608
#define D_HID  4608
#define D_OUT  1152
#define KDIM   4608      // K for BOTH gemms (D_IN == D_HID)

// ---------------- GEMM tiling (fp16 mma.sync.m16n8k16) ----------------
#define BM 128
#define BN 128
#define BK 128
#define NKT (KDIM / BK)             // 36
#define NTHREADS 512
#define GROUP 8                     // supertile height for L2 reuse
#define NPART1 (D_HID / BN)         // 36
#define NCH 64                      // colsq K-chunks

#define OFF_AMU 0u
#define OFF_ASG 32768u
#define OFF_B   65536u
#define STAGE_B 98304u
#define NSTAGE  2
#define SMEM_ALLOC (NSTAGE * 98304)   // 196608 bytes

// ---------------- device scratch (allocation-free rule) ----------------
__device__ __half g_amuh[(size_t)M_ROWS * D_IN];
__device__ __half g_asgh[(size_t)M_ROWS * D_IN];
__device__ __half g_hmuh[(size_t)M_ROWS * D_HID];
__device__ __half g_hsgh[(size_t)M_ROWS * D_HID];
__device__ __half g_w1h [(size_t)D_IN * D_HID];
__device__ __half g_w2h [(size_t)D_HID * D_OUT];
__device__ float  g_rowstat1[M_ROWS];
__device__ float  g_rowstat2[M_ROWS];
__device__ float  g_part2[NPART1 * M_ROWS];
__device__ float  g_ws1[D_HID];
__device__ float  g_ws2[D_OUT];
__device__ float  g_csq1[NCH * D_HID];
__device__ float  g_csq2[NCH * D_OUT];
__device__ int    g_mask_kind;       // 0=u8, 1=i32, 2=f32

// ---------------- helpers ----------------
__device__ __forceinline__ float cleanf(float x) {
    if (isnan(x)) return 1e-5f;
    if (isinf(x)) return 1.0f;
    return x;
}
__device__ __forceinline__ float softplusf(float x) {
    return (x > 20.0f) ? x : log1pf(expf(x));
}
__device__ __forceinline__ float fetch_mask(const void* p, size_t i, int kind) {
    if (kind == 2) return ((const float*)p)[i];
    if (kind == 1) return (float)(((const int*)p)[i]);
    return (float)(((const unsigned char*)p)[i]);
}
__device__ __forceinline__ uint32_t smaddr(const void* p) {
    return (uint32_t)__cvta_generic_to_shared(p);
}
__device__ __forceinline__ void cpasync16(uint32_t s, const void* g) {
    asm volatile("cp.async.cg.shared.global [%0], [%1], 16;\n" :: "r"(s), "l"(g));
}
__device__ __forceinline__ void ldsm4(uint32_t r[4], uint32_t a) {
    asm volatile("ldmatrix.sync.aligned.m8n8.x4.shared.b16 {%0,%1,%2,%3}, [%4];"
        : "=r"(r[0]), "=r"(r[1]), "=r"(r[2]), "=r"(r[3]) : "r"(a));
}
__device__ __forceinline__ void ldsm4t(uint32_t r[4], uint32_t a) {
    asm volatile("ldmatrix.sync.aligned.m8n8.x4.trans.shared.b16 {%0,%1,%2,%3}, [%4];"
        : "=r"(r[0]), "=r"(r[1]), "=r"(r[2]), "=r"(r[3]) : "r"(a));
}
__device__ __forceinline__ void mma16816(float c[4], const uint32_t a[4], uint32_t b0, uint32_t b1) {
    asm volatile(
        "mma.sync.aligned.m16n8k16.row.col.f32.f16.f16.f32 "
        "{%0,%1,%2,%3}, {%4,%5,%6,%7}, {%8,%9}, {%0,%1,%2,%3};\n"
        : "+f"(c[0]), "+f"(c[1]), "+f"(c[2]), "+f"(c[3])
        : "r"(a[0]), "r"(a[1]), "r"(a[2]), "r"(a[3]), "r"(b0), "r"(b1));
}
__device__ __forceinline__ uint32_t hsq2(uint32_t b) {   // fp16x2 elementwise square
    __half2 h = *reinterpret_cast<__half2*>(&b);
    h = __hmul2(h, h);
    return *reinterpret_cast<uint32_t*>(&h);
}

// ---------------- mask dtype detection ----------------
__global__ void detect_k(const unsigned int* m) {
    if (threadIdx.x != 0) return;
    bool f32ok = true, i32ok = true, any_f = false, any_i = false;
    for (int i = 0; i < 64; ++i) {
        unsigned w = m[i];
        if (w == 0x3F800000u) { any_f = true; i32ok = false; }
        else if (w == 1u)     { any_i = true; f32ok = false; }
        else if (w != 0u)     { f32ok = false; i32ok = false; }
    }
    int kind;
    if (f32ok && any_f)      kind = 2;
    else if (i32ok && any_i) kind = 1;
    else                     kind = 0;
    g_mask_kind = kind;
}

// ---------------- softplus of w_sigma ----------------
__global__ void ws_k(const float* __restrict__ s1, const float* __restrict__ s2) {
    int i = blockIdx.x * 256 + threadIdx.x;
    if (i < D_HID) g_ws1[i] = softplusf(s1[i]);
    if (i < D_OUT) g_ws2[i] = softplusf(s2[i]);
}

// ---------------- fused: fp32->fp16 weight conversion + column sums of w^2 --
// Single pass over W: writes fp16 copy AND accumulates per-chunk colsq partial.
template <int L>
__global__ void convcolsq_k(const float* __restrict__ w) {
    const int N = (L == 1) ? D_HID : D_OUT;
    const int K = (L == 1) ? D_IN : D_HID;
    __half* wh = (L == 1) ? g_w1h : g_w2h;
    const int col = blockIdx.x * 128 + threadIdx.x;
    const int kc = K / NCH;
    const int kb = blockIdx.y * kc;
    float s = 0.f;
    #pragma unroll 4
    for (int k = kb; k < kb + kc; ++k) {
        float v = w[(size_t)k * N + col];
        s += v * v;
        wh[(size_t)k * N + col] = __float2half_rn(v);
    }
    if (L == 1) g_csq1[blockIdx.y * D_HID + col] = s;
    else        g_csq2[blockIdx.y * D_OUT + col] = s;
}

// ---------------- KL scalar ----------------
__global__ void kl_k(float* __restrict__ out) {
    __shared__ float red[512];
    const int t = threadIdx.x;
    float v = 0.f;
    for (int j = t; j < D_HID; j += 512) {
        float w = g_ws1[j];
        float cs = 0.f;
        #pragma unroll
        for (int c = 0; c < NCH; ++c) cs += g_csq1[c * D_HID + j];
        v += (4608.0f * w + cs - 4608.0f - 4608.0f * logf(w)) * (1.0f / (float)D_HID);
    }
    for (int j = t; j < D_OUT; j += 512) {
        float w = g_ws2[j];
        float cs = 0.f;
        #pragma unroll
        for (int c = 0; c < NCH; ++c) cs += g_csq2[c * D_OUT + j];
        v += (4608.0f * w + cs - 4608.0f - 4608.0f * logf(w)) * (1.0f / (float)D_OUT);
    }
    red[t] = v;
    __syncthreads();
    for (int s = 256; s; s >>= 1) {
        if (t < s) red[t] += red[t + s];
        __syncthreads();
    }
    if (t == 0) out[0] = 0.5f * red[0];
}

// ---------------- fused: rowstat1 + fp32->fp16 input conversion -------------
__global__ void rowstat1_conv_k(const float* __restrict__ mu, const float* __restrict__ sg) {
    const int w = (blockIdx.x * blockDim.x + threadIdx.x) >> 5;
    const int lane = threadIdx.x & 31;
    if (w >= M_ROWS) return;
    const size_t base = (size_t)w * D_IN;
    const float4* m4 = (const float4*)(mu + base);
    const float4* s4 = (const float4*)(sg + base);
    float s = 0.f;
    for (int i = lane; i < D_IN / 4; i += 32) {
        float4 a = m4[i];
        s += a.x * a.x + a.y * a.y + a.z * a.z + a.w * a.w;
        float4 b = s4[i];
        s += b.x + b.y + b.z + b.w;
        const size_t g = base + (size_t)i * 4;
        *(__half2*)(g_amuh + g)     = __floats2half2_rn(a.x, a.y);
        *(__half2*)(g_amuh + g + 2) = __floats2half2_rn(a.z, a.w);
        *(__half2*)(g_asgh + g)     = __floats2half2_rn(b.x, b.y);
        *(__half2*)(g_asgh + g + 2) = __floats2half2_rn(b.z, b.w);
    }
    #pragma unroll
    for (int o = 16; o; o >>= 1) s += __shfl_xor_sync(0xffffffffu, s, o);
    if (lane == 0) g_rowstat1[w] = s;
}

// ---------------- reduce GEMM1 partials -> rowstat2 ----------------
__global__ void rowstat2_k() {
    int r = blockIdx.x * blockDim.x + threadIdx.x;
    if (r < M_ROWS) {
        float s = 0.f;
        #pragma unroll 4
        for (int c = 0; c < NPART1; ++c) s += g_part2[c * M_ROWS + r];
        g_rowstat2[r] = s;
    }
}

// ============================================================================
// Dual-accumulator fp16 tensor-core GEMM (W∘W derived in registers).
// A tiles: [128 x 128] fp16, 256B rows, XOR swizzle (c ^ (r&7)), c in 0..15
// B tiles: [128 x 128] fp16 ([K,N] layout), 256B rows, same swizzle
// 2-stage pipeline, prefetch depth 1: wait; sync; load(t+1); compute(t).
// PHASE 1: Sigma + clean + GELU + dropout1 -> fp16 hidden + per-row partials.
// PHASE 2: Sigma + clean + dropout2 -> fp32 outputs.
// ============================================================================
template <int PHASE>
__global__ void __launch_bounds__(NTHREADS, 1) gemm_h(
    const void* __restrict__ mask, float* __restrict__ outMu, float* __restrict__ outSig,
    int tilesN)
{
    extern __shared__ char smem[];
    const uint32_t sbase = smaddr(smem);
    float* shf = (float*)smem;

    const __half* __restrict__ Amu = (PHASE == 1) ? g_amuh : g_hmuh;
    const __half* __restrict__ Asg = (PHASE == 1) ? g_asgh : g_hsgh;
    const __half* __restrict__ Bh  = (PHASE == 1) ? g_w1h : g_w2h;
    const float* __restrict__ ws   = (PHASE == 1) ? g_ws1 : g_ws2;
    const int HN = (PHASE == 1) ? D_HID : D_OUT;

    const int tid   = threadIdx.x;
    const int warpId = tid >> 5;
    const int lane  = tid & 31;
    const int warpM = warpId & 3;
    const int warpN = warpId >> 2;
    const int gid   = lane >> 2;
    const int tid4  = lane & 3;

    // supertile rasterization for L2 reuse
    const int per = GROUP * tilesN;
    const int gi = blockIdx.x / per, rr = blockIdx.x % per;
    const int tm = gi * GROUP + (rr % GROUP);
    const int tn = rr / GROUP;
    const int rowBase = tm * BM;
    const int colBase = tn * BN;

    float accmu[2][4][4];
    float accsg[2][4][4];
    #pragma unroll
    for (int mi = 0; mi < 2; ++mi)
        #pragma unroll
        for (int ni = 0; ni < 4; ++ni)
            #pragma unroll
            for (int j = 0; j < 4; ++j) { accmu[mi][ni][j] = 0.f; accsg[mi][ni][j] = 0.f; }

    auto load_tile = [&](int t) {
        const uint32_t sb = sbase + (uint32_t)(t & (NSTAGE - 1)) * STAGE_B;
        const int k0 = t * BK;
        // A tiles: 128 rows x 16 chunks (16B) = 2048 chunks per operand
        #pragma unroll
        for (int it = 0; it < 4; ++it) {
            int id = tid + it * NTHREADS;
            int r = id >> 4, c = id & 15;
            uint32_t sa = sb + (uint32_t)(r * 256 + ((c ^ (r & 7)) << 4));
            const size_t g = (size_t)(rowBase + r) * KDIM + k0 + c * 8;
            cpasync16(sa + OFF_AMU, Amu + g);
            cpasync16(sa + OFF_ASG, Asg + g);
        }
        // B tile: 128 rows x 16 chunks (16B) = 2048 chunks
        #pragma unroll
        for (int it = 0; it < 4; ++it) {
            int id = tid + it * NTHREADS;
            int r = id >> 4, c = id & 15;
            uint32_t sa = sb + (uint32_t)(r * 256 + ((c ^ (r & 7)) << 4));
            cpasync16(sa + OFF_B, Bh + (size_t)(k0 + r) * HN + colBase + c * 8);
        }
        asm volatile("cp.async.commit_group;\n" ::: "memory");
    };

    load_tile(0);

    for (int t = 0; t < NKT; ++t) {
        asm volatile("cp.async.wait_group 0;\n" ::: "memory");
        __syncthreads();
        if (t + 1 < NKT) load_tile(t + 1);   // overlaps with compute(t)

        const uint32_t sb = sbase + (uint32_t)(t & (NSTAGE - 1)) * STAGE_B;
        #pragma unroll
        for (int ks = 0; ks < 8; ++ks) {
            uint32_t amu[2][4], asg[2][4];
            #pragma unroll
            for (int mi = 0; mi < 2; ++mi) {
                int r = warpM * 32 + mi * 16 + (lane & 15);
                int c = ks * 2 + (lane >> 4);
                uint32_t ad = sb + (uint32_t)(r * 256 + ((c ^ (r & 7)) << 4));
                ldsm4(amu[mi], ad + OFF_AMU);
                ldsm4(asg[mi], ad + OFF_ASG);
            }
            #pragma unroll
            for (int np = 0; np < 2; ++np) {
                int r = ks * 16 + (lane & 15);
                int c = warpN * 4 + np * 2 + (lane >> 4);
                uint32_t ad = sb + (uint32_t)(r * 256 + ((c ^ (r & 7)) << 4));
                uint32_t bb[4];
                ldsm4t(bb, ad + OFF_B);
                uint32_t bq0 = hsq2(bb[0]), bq1 = hsq2(bb[1]);
                uint32_t bq2 = hsq2(bb[2]), bq3 = hsq2(bb[3]);
                #pragma unroll
                for (int mi = 0; mi < 2; ++mi) {
                    mma16816(accmu[mi][np * 2 + 0], amu[mi], bb[0], bb[1]);
                    mma16816(accmu[mi][np * 2 + 1], amu[mi], bb[2], bb[3]);
                    mma16816(accsg[mi][np * 2 + 0], asg[mi], bq0, bq1);
                    mma16816(accsg[mi][np * 2 + 1], asg[mi], bq2, bq3);
                }
            }
        }
    }
    __syncthreads();

    const int kind = g_mask_kind;

    if (PHASE == 1) {
        // ---- layer-1 epilogue: Sigma + clean + GELU + dropout1 -> fp16 hidden
        #pragma unroll
        for (int mi = 0; mi < 2; ++mi) {
            #pragma unroll
            for (int h = 0; h < 2; ++h) {
                const int rloc = warpM * 32 + mi * 16 + h * 8 + gid;
                const int row = rowBase + rloc;
                const float rs = g_rowstat1[row];
                float acc = 0.f;
                #pragma unroll
                for (int ni = 0; ni < 4; ++ni) {
                    const int col = colBase + warpN * 32 + ni * 8 + tid4 * 2;
                    float mu0 = accmu[mi][ni][2 * h];
                    float mu1 = accmu[mi][ni][2 * h + 1];
                    float S0 = cleanf(accsg[mi][ni][2 * h]     + rs * ws[col]);
                    float S1 = cleanf(accsg[mi][ni][2 * h + 1] + rs * ws[col + 1]);
                    float cdf0 = 0.5f * (1.0f + erff(mu0 * 0.70710678118654752f));
                    float gr0  = cdf0 + mu0 * (expf(-0.5f * mu0 * mu0) * 0.3989422804014327f);
                    float cdf1 = 0.5f * (1.0f + erff(mu1 * 0.70710678118654752f));
                    float gr1  = cdf1 + mu1 * (expf(-0.5f * mu1 * mu1) * 0.3989422804014327f);
                    float gm0 = mu0 * cdf0, gm1 = mu1 * cdf1;
                    float gs0 = gr0 * gr0 * S0, gs1 = gr1 * gr1 * S1;
                    size_t idx = (size_t)row * D_HID + col;
                    float m0 = fetch_mask(mask, idx, kind);
                    float m1 = fetch_mask(mask, idx + 1, kind);
                    float hm0 = gm0 * m0 * (1.0f / 0.9f);
                    float hm1 = gm1 * m1 * (1.0f / 0.9f);
                    float hs0 = cleanf(gs0 * m0 * (1.0f / (float)D_HID));
                    float hs1 = cleanf(gs1 * m1 * (1.0f / (float)D_HID));
                    __half2 hm2 = __floats2half2_rn(hm0, hm1);
                    __half2 hs2 = __floats2half2_rn(hs0, hs1);
                    *(__half2*)(g_hmuh + idx) = hm2;
                    *(__half2*)(g_hsgh + idx) = hs2;
                    // fp16-rounded values so rowstat2 matches GEMM2's operands
                    float rm0 = __low2float(hm2), rm1 = __high2float(hm2);
                    float rs0 = __low2float(hs2), rs1 = __high2float(hs2);
                    acc += rm0 * rm0 + rm1 * rm1 + rs0 + rs1;
                }
                acc += __shfl_xor_sync(0xffffffffu, acc, 1);
                acc += __shfl_xor_sync(0xffffffffu, acc, 2);
                if (tid4 == 0) shf[warpN * BM + rloc] = acc;
            }
        }
        __syncthreads();
        if (tid < BM) {
            float s = shf[tid] + shf[BM + tid] + shf[2 * BM + tid] + shf[3 * BM + tid];
            g_part2[(size_t)tn * M_ROWS + rowBase + tid] = s;
        }
    } else {
        // ---- layer-2 epilogue: Sigma + clean + dropout2 -> fp32 outputs
        #pragma unroll
        for (int mi = 0; mi < 2; ++mi) {
            #pragma unroll
            for (int h = 0; h < 2; ++h) {
                const int row = rowBase + warpM * 32 + mi * 16 + h * 8 + gid;
                const float rs = g_rowstat2[row];
                #pragma unroll
                for (int ni = 0; ni < 4; ++ni) {
                    const int col = colBase + warpN * 32 + ni * 8 + tid4 * 2;
                    float mu0 = accmu[mi][ni][2 * h];
                    float mu1 = accmu[mi][ni][2 * h + 1];
                    float S0 = cleanf(accsg[mi][ni][2 * h]     + rs * ws[col]);
                    float S1 = cleanf(accsg[mi][ni][2 * h + 1] + rs * ws[col + 1]);
                    size_t idx = (size_t)row * D_OUT + col;
                    float m0 = fetch_mask(mask, idx, kind);
                    float m1 = fetch_mask(mask, idx + 1, kind);
                    float2 v;
                    v.x = mu0 * m0 * (1.0f / 0.9f);
                    v.y = mu1 * m1 * (1.0f / 0.9f);
                    float2 w;
                    w.x = cleanf(S0 * m0 * (1.0f / (float)D_OUT));
                    w.y = cleanf(S1 * m1 * (1.0f / (float)D_OUT));
                    *reinterpret_cast<float2*>(&outMu[idx]) = v;
                    *reinterpret_cast<float2*>(&outSig[idx]) = w;
                }
            }
        }
    }
}

// ============================================================================
extern "C" void kernel_launch(void* const* d_in, const int* in_sizes, int n_in,
                              void* d_out, int out_size) {
    const float* mu_in  = (const float*)d_in[0];
    const float* sg_in  = (const float*)d_in[1];
    const void*  mask1  = d_in[2];
    const void*  mask2  = d_in[3];
    const float* w1     = (const float*)d_in[4];
    const float* wsig1  = (const float*)d_in[5];
    const float* w2     = (const float*)d_in[6];
    const float* wsig2  = (const float*)d_in[7];
    float* out = (float*)d_out;

    // Output layout: [mu (M*D_OUT)] [sigma (M*D_OUT)] [kl (1)]
    const int half = (out_size - 1) / 2;
    float* out_mu  = out;
    float* out_sig = out + half;
    float* out_kl  = out + (out_size - 1);

    cudaFuncSetAttribute(gemm_h<1>, cudaFuncAttributeMaxDynamicSharedMemorySize, SMEM_ALLOC);
    cudaFuncSetAttribute(gemm_h<2>, cudaFuncAttributeMaxDynamicSharedMemorySize, SMEM_ALLOC);

    detect_k<<<1, 32>>>((const unsigned int*)mask1);
    ws_k<<<(D_HID + 255) / 256, 256>>>(wsig1, wsig2);
    convcolsq_k<1><<<dim3(D_HID / 128, NCH), 128>>>(w1);
    convcolsq_k<2><<<dim3(D_OUT / 128, NCH), 128>>>(w2);
    kl_k<<<1, 512>>>(out_kl);
    rowstat1_conv_k<<<(M_ROWS * 32) / 256, 256>>>(mu_in, sg_in);

    gemm_h<1><<<(M_ROWS / BM) * (D_HID / BN), NTHREADS, SMEM_ALLOC>>>(
        mask1, nullptr, nullptr, D_HID / BN);

    rowstat2_k<<<M_ROWS / 256, 256>>>();

    gemm_h<2><<<(M_ROWS / BM) * (D_OUT / BN), NTHREADS, SMEM_ALLOC>>>(
        mask2, out_mu, out_sig, D_OUT / BN);
}